// round 13
// baseline (speedup 1.0000x reference)
#include <cuda_runtime.h>
#include <cuda_fp16.h>
#include <cstdint>

#define B_DIM 256
#define D_DIM 65536
#define N_DIM 41
#define G_DIM 2048
#define O_DIM 256
#define E_DIM 512
#define NO_DIM (N_DIM * O_DIM)
#define NEG_SLOPE 0.2f

// statics ~59 MB
__device__ unsigned short g_xT[(size_t)D_DIM * B_DIM];     // 32 MB fp16 bits
__device__ unsigned short g_H[(size_t)B_DIM * NO_DIM];     // 5.4 MB fp16 bits
__device__ float g_P[(size_t)N_DIM * B_DIM * E_DIM];       // 21.5 MB

// ---------------------------------------------------------------- helpers
__device__ __forceinline__ uint32_t sptr(const void* p) {
    return (uint32_t)__cvta_generic_to_shared(p);
}
__device__ __forceinline__ void ldsm4t(uint32_t* r, uint32_t a) {
    asm volatile("ldmatrix.sync.aligned.m8n8.x4.trans.shared.b16 {%0,%1,%2,%3},[%4];"
                 : "=r"(r[0]), "=r"(r[1]), "=r"(r[2]), "=r"(r[3]) : "r"(a));
}
__device__ __forceinline__ void ldsm4(uint32_t* r, uint32_t a) {
    asm volatile("ldmatrix.sync.aligned.m8n8.x4.shared.b16 {%0,%1,%2,%3},[%4];"
                 : "=r"(r[0]), "=r"(r[1]), "=r"(r[2]), "=r"(r[3]) : "r"(a));
}
__device__ __forceinline__ void mma16816h(float* c, const uint32_t* a, const uint32_t* b) {
    asm volatile("mma.sync.aligned.m16n8k16.row.col.f32.f16.f16.f32 "
                 "{%0,%1,%2,%3},{%4,%5,%6,%7},{%8,%9},{%0,%1,%2,%3};"
                 : "+f"(c[0]), "+f"(c[1]), "+f"(c[2]), "+f"(c[3])
                 : "r"(a[0]), "r"(a[1]), "r"(a[2]), "r"(a[3]), "r"(b[0]), "r"(b[1]));
}
__device__ __forceinline__ uint32_t pack2h(float a, float b) {
    return (uint32_t)__half_as_ushort(__float2half_rn(a)) |
           ((uint32_t)__half_as_ushort(__float2half_rn(b)) << 16);
}

// ---------------------------------------------------------------- transpose x -> fp16 xT [D][B]
__global__ __launch_bounds__(256) void transpose_kernel(const float* __restrict__ x) {
    __shared__ float tile[64][65];
    int d0 = blockIdx.x * 64, b0 = blockIdx.y * 64;
    int t = threadIdx.x;
    int br = t / 16, dc = (t % 16) * 4;
#pragma unroll
    for (int p = 0; p < 4; p++) {
        int b = br + p * 16;
        float4 v = *(const float4*)&x[(size_t)(b0 + b) * D_DIM + d0 + dc];
        tile[b][dc] = v.x; tile[b][dc+1] = v.y; tile[b][dc+2] = v.z; tile[b][dc+3] = v.w;
    }
    __syncthreads();
    int dr = t / 16, bc = (t % 16) * 4;
#pragma unroll
    for (int p = 0; p < 4; p++) {
        int d = dr + p * 16;
        size_t off = (size_t)(d0 + d) * B_DIM + b0 + bc;
        *(uint2*)&g_xT[off] = make_uint2(pack2h(tile[bc][d],   tile[bc+1][d]),
                                         pack2h(tile[bc+2][d], tile[bc+3][d]));
    }
}

// ---------------------------------------------------------------- GEMM1 (fp16, tile 64x64, BK=32, prefetch-2, occ 2)
// warps: 4 m x 2 n; warp tile 16x32
__global__ __launch_bounds__(256, 2) void gemm1_kernel(
    const int* __restrict__ gidx, const float* __restrict__ W, const float* __restrict__ bias)
{
    __shared__ unsigned short sIdx[G_DIM];                    // 4 KB
    __shared__ alignas(16) unsigned short As[2][32][72];      // 9.2 KB [k][m]
    __shared__ alignas(16) unsigned short Bs[2][32][72];      // 9.2 KB [k][o]

    const int n     = blockIdx.z;
    const int bbase = blockIdx.x * 64;
    const int obase = blockIdx.y * 64;
    const int tid = threadIdx.x, lane = tid & 31, warp = tid >> 5;
    const int wm = (warp & 3) * 16, wn = (warp >> 2) * 32;
    const int arow = tid >> 3, acol = (tid & 7) * 8;    // A: 32 k-rows x 8 halves
    const int brow = tid >> 3, bcol = (tid & 7) * 4;    // B: 32 k-rows x (2x float4)

    for (int i = tid; i < G_DIM; i += 256)
        sIdx[i] = (unsigned short)gidx[(size_t)n * G_DIM + i];
    __syncthreads();

    const float* Wn = W + (size_t)n * G_DIM * O_DIM;
    const int g8 = lane >> 3, i8 = lane & 7;
    const int a_krow = (g8 >> 1) * 8 + i8, a_mcol = (g8 & 1) * 8;
    const int b_krow = (g8 & 1) * 8 + i8, b_ncol = (g8 >> 1) * 8;

    float acc[4][4];
#pragma unroll
    for (int i = 0; i < 4; i++)
#pragma unroll
        for (int q = 0; q < 4; q++) acc[i][q] = 0.0f;

    auto ldg = [&](int ch, uint4& a0, float4& w0, float4& w1) {
        int k0 = ch * 32;
        int gi = sIdx[k0 + arow];
        a0 = *(const uint4*)&g_xT[(size_t)gi * B_DIM + bbase + acol];
        const float* wr = &Wn[(size_t)(k0 + brow) * O_DIM + obase + bcol];
        w0 = *(const float4*)wr;
        w1 = *(const float4*)(wr + 32);
    };
    auto sts = [&](int buf, uint4 a0, float4 w0, float4 w1) {
        *(uint4*)&As[buf][arow][acol]      = a0;
        *(uint2*)&Bs[buf][brow][bcol]      = make_uint2(pack2h(w0.x, w0.y), pack2h(w0.z, w0.w));
        *(uint2*)&Bs[buf][brow][bcol + 32] = make_uint2(pack2h(w1.x, w1.y), pack2h(w1.z, w1.w));
    };
    auto compute = [&](int buf) {
#pragma unroll
        for (int ks = 0; ks < 2; ks++) {
            uint32_t af[4], bfv[2][4];
            ldsm4t(af, sptr(&As[buf][ks * 16 + a_krow][wm + a_mcol]));
#pragma unroll
            for (int np = 0; np < 2; np++)
                ldsm4t(bfv[np], sptr(&Bs[buf][ks * 16 + b_krow][wn + np * 16 + b_ncol]));
#pragma unroll
            for (int nt = 0; nt < 4; nt++)
                mma16816h(acc[nt], af, &bfv[nt >> 1][(nt & 1) * 2]);
        }
    };

    uint4 A0, A1;
    float4 W00, W01, W10, W11;
    ldg(0, A0, W00, W01);
    sts(0, A0, W00, W01);
    ldg(1, A0, W00, W01);
    __syncthreads();

    const int NCHUNK = G_DIM / 32;  // 64
    for (int ch = 0; ch < NCHUNK; ch += 2) {
        if (ch + 2 < NCHUNK) ldg(ch + 2, A1, W10, W11);
        compute(0);
        sts(1, A0, W00, W01);
        __syncthreads();
        if (ch + 3 < NCHUNK) ldg(ch + 3, A0, W00, W01);
        compute(1);
        if (ch + 2 < NCHUNK) sts(0, A1, W10, W11);
        __syncthreads();
    }

    // epilogue: H -> fp16, row-major [B][NO]
    const int r = lane >> 2, c = (lane & 3) * 2;
#pragma unroll
    for (int nt = 0; nt < 4; nt++) {
        int ocol = obase + wn + nt * 8 + c;
        float bv0 = bias[n * O_DIM + ocol], bv1 = bias[n * O_DIM + ocol + 1];
        int b0 = bbase + wm + r;
#pragma unroll
        for (int q = 0; q < 2; q++) {
            size_t base = (size_t)(b0 + q*8) * NO_DIM + (size_t)n * O_DIM + ocol;
            *(uint32_t*)&g_H[base] = pack2h(acc[nt][q*2] + bv0, acc[nt][q*2+1] + bv1);
        }
    }
}

// ---------------------------------------------------------------- GEMM2 split-K (fp16, tile 64x128, BK=16, prefetch-2, occ 2)
// warps: 4 m x 2 n; warp tile 16x64
__global__ __launch_bounds__(256, 2) void gemm2_kernel(const float* __restrict__ W3)
{
    __shared__ alignas(16) unsigned short As[2][64][24];    // 6 KB [m][k]
    __shared__ alignas(16) unsigned short Bs[2][16][136];   // 8.5 KB [k][e]

    const int s = blockIdx.z, bbase = blockIdx.x * 64, ebase = blockIdx.y * 128;
    const int tid = threadIdx.x, lane = tid & 31, warp = tid >> 5;
    const int wm = (warp & 3) * 16, wn = (warp >> 2) * 64;
    const int arow = tid >> 2, ahalf = (tid & 3) * 4;       // A: 64 rows x 4 halves
    const int kkB = tid >> 5, colB = (tid & 31) * 4;
    const int g8 = lane >> 3, i8 = lane & 7;
    const int a_mrow = (g8 & 1) * 8 + i8, a_kcol = (g8 >> 1) * 8;
    const int b_krow = (g8 & 1) * 8 + i8, b_ncol = (g8 >> 1) * 8;

    float acc[8][4];
#pragma unroll
    for (int i = 0; i < 8; i++)
#pragma unroll
        for (int q = 0; q < 4; q++) acc[i][q] = 0.0f;

    const int kbeg = s * 256;

    auto ldg = [&](int ch, uint2& ah, float4& p0, float4& p1) {
        int k0 = kbeg + ch * 16;
        ah = *(const uint2*)&g_H[(size_t)(bbase + arow) * NO_DIM + k0 + ahalf];
        p0 = *(const float4*)&W3[(size_t)(k0 + kkB) * E_DIM + ebase + colB];
        p1 = *(const float4*)&W3[(size_t)(k0 + kkB + 8) * E_DIM + ebase + colB];
    };
    auto sts = [&](int buf, uint2 ah, float4 p0, float4 p1) {
        *(uint2*)&As[buf][arow][ahalf] = ah;
        *(uint2*)&Bs[buf][kkB][colB]     = make_uint2(pack2h(p0.x, p0.y), pack2h(p0.z, p0.w));
        *(uint2*)&Bs[buf][kkB + 8][colB] = make_uint2(pack2h(p1.x, p1.y), pack2h(p1.z, p1.w));
    };
    auto compute = [&](int buf) {
        uint32_t af[4], bfv[4][4];
        ldsm4(af, sptr(&As[buf][wm + a_mrow][a_kcol]));
#pragma unroll
        for (int np = 0; np < 4; np++)
            ldsm4t(bfv[np], sptr(&Bs[buf][b_krow][wn + np * 16 + b_ncol]));
#pragma unroll
        for (int nt = 0; nt < 8; nt++)
            mma16816h(acc[nt], af, &bfv[nt >> 1][(nt & 1) * 2]);
    };

    uint2 Ah0, Ah1;
    float4 B00, B01, B10, B11;
    ldg(0, Ah0, B00, B01);
    sts(0, Ah0, B00, B01);
    ldg(1, Ah0, B00, B01);
    __syncthreads();

    const int NCHUNK = 16;
    for (int ch = 0; ch < NCHUNK; ch += 2) {
        if (ch + 2 < NCHUNK) ldg(ch + 2, Ah1, B10, B11);
        compute(0);
        sts(1, Ah0, B00, B01);
        __syncthreads();
        if (ch + 3 < NCHUNK) ldg(ch + 3, Ah0, B00, B01);
        compute(1);
        if (ch + 2 < NCHUNK) sts(0, Ah1, B10, B11);
        __syncthreads();
    }

    float* Ps = g_P + (size_t)s * B_DIM * E_DIM;
    const int r = lane >> 2, c = (lane & 3) * 2;
#pragma unroll
    for (int nt = 0; nt < 8; nt++) {
        int ecol = ebase + wn + nt * 8 + c;
        int b0 = bbase + wm + r;
        *(float2*)&Ps[(size_t)b0 * E_DIM + ecol]       = make_float2(acc[nt][0], acc[nt][1]);
        *(float2*)&Ps[(size_t)(b0 + 8) * E_DIM + ecol] = make_float2(acc[nt][2], acc[nt][3]);
    }
}

// ---------------------------------------------------------------- reduce
__global__ __launch_bounds__(256) void reduce_kernel(const float* __restrict__ b3, float* __restrict__ out) {
    int i4 = blockIdx.x * 256 + threadIdx.x;
    int e4 = i4 & (E_DIM / 4 - 1);
    float4 sum = ((const float4*)b3)[e4];
#pragma unroll
    for (int s = 0; s < N_DIM; s++) {
        float4 p = ((const float4*)g_P)[(size_t)s * (B_DIM * E_DIM / 4) + i4];
        sum.x += p.x; sum.y += p.y; sum.z += p.z; sum.w += p.w;
    }
    sum.x = (sum.x >= 0.f) ? sum.x : NEG_SLOPE * sum.x;
    sum.y = (sum.y >= 0.f) ? sum.y : NEG_SLOPE * sum.y;
    sum.z = (sum.z >= 0.f) ? sum.z : NEG_SLOPE * sum.z;
    sum.w = (sum.w >= 0.f) ? sum.w : NEG_SLOPE * sum.w;
    ((float4*)out)[i4] = sum;
}

// ----------------------------------------------------------------
extern "C" void kernel_launch(void* const* d_in, const int* in_sizes, int n_in,
                              void* d_out, int out_size) {
    const float* x    = (const float*)d_in[0];
    const int*   gidx = (const int*)  d_in[1];
    const float* W    = (const float*)d_in[2];
    const float* bias = (const float*)d_in[3];
    const float* W3   = (const float*)d_in[4];
    const float* b3   = (const float*)d_in[5];
    float* out = (float*)d_out;

    {
        dim3 grid(D_DIM / 64, B_DIM / 64);
        transpose_kernel<<<grid, 256>>>(x);
    }
    {
        dim3 grid(B_DIM / 64, O_DIM / 64, N_DIM);     // (4,4,41) = 656 CTAs
        gemm1_kernel<<<grid, 256>>>(gidx, W, bias);
    }
    {
        dim3 grid(B_DIM / 64, E_DIM / 128, N_DIM);    // (4,4,41) = 656 CTAs
        gemm2_kernel<<<grid, 256>>>(W3);
    }
    {
        reduce_kernel<<<(B_DIM * E_DIM / 4) / 256, 256>>>(b3, out);
    }
}

// round 14
// speedup vs baseline: 1.3790x; 1.3790x over previous
#include <cuda_runtime.h>
#include <cuda_fp16.h>
#include <cstdint>

#define B_DIM 256
#define D_DIM 65536
#define N_DIM 41
#define G_DIM 2048
#define KSPL  1024        // gemm1 K per split
#define O_DIM 256
#define E_DIM 512
#define NO_DIM (N_DIM * O_DIM)
#define NEG_SLOPE 0.2f

// statics ~64.5 MB
__device__ unsigned short g_xT[(size_t)D_DIM * B_DIM];     // 32 MB fp16 bits
__device__ unsigned short g_H0[(size_t)B_DIM * NO_DIM];    // 5.4 MB fp16 partial (k 0..1023)
__device__ unsigned short g_H1[(size_t)B_DIM * NO_DIM];    // 5.4 MB fp16 partial (k 1024..2047)
__device__ float g_P[(size_t)N_DIM * B_DIM * E_DIM];       // 21.5 MB

// ---------------------------------------------------------------- helpers
__device__ __forceinline__ uint32_t sptr(const void* p) {
    return (uint32_t)__cvta_generic_to_shared(p);
}
__device__ __forceinline__ void ldsm4t(uint32_t* r, uint32_t a) {
    asm volatile("ldmatrix.sync.aligned.m8n8.x4.trans.shared.b16 {%0,%1,%2,%3},[%4];"
                 : "=r"(r[0]), "=r"(r[1]), "=r"(r[2]), "=r"(r[3]) : "r"(a));
}
__device__ __forceinline__ void ldsm4(uint32_t* r, uint32_t a) {
    asm volatile("ldmatrix.sync.aligned.m8n8.x4.shared.b16 {%0,%1,%2,%3},[%4];"
                 : "=r"(r[0]), "=r"(r[1]), "=r"(r[2]), "=r"(r[3]) : "r"(a));
}
__device__ __forceinline__ void mma16816h(float* c, const uint32_t* a, const uint32_t* b) {
    asm volatile("mma.sync.aligned.m16n8k16.row.col.f32.f16.f16.f32 "
                 "{%0,%1,%2,%3},{%4,%5,%6,%7},{%8,%9},{%0,%1,%2,%3};"
                 : "+f"(c[0]), "+f"(c[1]), "+f"(c[2]), "+f"(c[3])
                 : "r"(a[0]), "r"(a[1]), "r"(a[2]), "r"(a[3]), "r"(b[0]), "r"(b[1]));
}
__device__ __forceinline__ uint32_t pack2h(float a, float b) {
    return (uint32_t)__half_as_ushort(__float2half_rn(a)) |
           ((uint32_t)__half_as_ushort(__float2half_rn(b)) << 16);
}
__device__ __forceinline__ uint32_t h2add(uint32_t a, uint32_t b) {
    __half2 r = __hadd2(*(__half2*)&a, *(__half2*)&b);
    return *(uint32_t*)&r;
}

// ---------------------------------------------------------------- transpose x -> fp16 xT [D][B]
__global__ __launch_bounds__(256) void transpose_kernel(const float* __restrict__ x) {
    __shared__ float tile[64][65];
    int d0 = blockIdx.x * 64, b0 = blockIdx.y * 64;
    int t = threadIdx.x;
    int br = t / 16, dc = (t % 16) * 4;
#pragma unroll
    for (int p = 0; p < 4; p++) {
        int b = br + p * 16;
        float4 v = *(const float4*)&x[(size_t)(b0 + b) * D_DIM + d0 + dc];
        tile[b][dc] = v.x; tile[b][dc+1] = v.y; tile[b][dc+2] = v.z; tile[b][dc+3] = v.w;
    }
    __syncthreads();
    int dr = t / 16, bc = (t % 16) * 4;
#pragma unroll
    for (int p = 0; p < 4; p++) {
        int d = dr + p * 16;
        size_t off = (size_t)(d0 + d) * B_DIM + b0 + bc;
        *(uint2*)&g_xT[off] = make_uint2(pack2h(tile[bc][d],   tile[bc+1][d]),
                                         pack2h(tile[bc+2][d], tile[bc+3][d]));
    }
}

// ---------------------------------------------------------------- GEMM1 (fp16, tile 128x64, BK=32, prefetch-2, occ 2, K-split 2)
// Hp[ks][b][n*256+o] = sum_{g in split ks} xT[idx][b] * W[n][g][o]  (+bias if ks==0)
__global__ __launch_bounds__(256, 2) void gemm1_kernel(
    const int* __restrict__ gidx, const float* __restrict__ W, const float* __restrict__ bias)
{
    __shared__ unsigned short sIdx[KSPL];                       // 2 KB
    __shared__ alignas(16) unsigned short As[2][32][136];       // 17.4 KB
    __shared__ alignas(16) unsigned short Bs[2][32][72];        // 9.2 KB

    const int zz    = blockIdx.z;
    const int n     = zz >> 1;
    const int ks    = zz & 1;
    const int kbeg  = ks * KSPL;
    const int bbase = blockIdx.x * 128;
    const int obase = blockIdx.y * 64;
    const int tid = threadIdx.x, lane = tid & 31, warp = tid >> 5;
    const int wm = (warp & 1) * 64, wn = (warp >> 1) * 16;
    const int arow = tid >> 3, acol = (tid & 7) * 8;
    const int brow = tid >> 3, bcol = (tid & 7) * 4;

    for (int i = tid; i < KSPL; i += 256)
        sIdx[i] = (unsigned short)gidx[(size_t)n * G_DIM + kbeg + i];
    __syncthreads();

    const float* Wn = W + (size_t)n * G_DIM * O_DIM + (size_t)kbeg * O_DIM;
    unsigned short* Hdst = ks ? g_H1 : g_H0;
    const int g8 = lane >> 3, i8 = lane & 7;
    const int a_krow = (g8 >> 1) * 8 + i8, a_mcol = (g8 & 1) * 8;
    const int b_krow = (g8 & 1) * 8 + i8, b_ncol = (g8 >> 1) * 8;

    float acc[4][2][4];
#pragma unroll
    for (int i = 0; i < 4; i++)
#pragma unroll
        for (int j = 0; j < 2; j++)
#pragma unroll
            for (int q = 0; q < 4; q++) acc[i][j][q] = 0.0f;

    auto ldg = [&](int ch, uint4& a0, uint4& a1, float4& w0, float4& w1) {
        int k0 = ch * 32;
        int gi = sIdx[k0 + arow];
        const unsigned short* xr = &g_xT[(size_t)gi * B_DIM + bbase + acol];
        a0 = *(const uint4*)xr;
        a1 = *(const uint4*)(xr + 64);
        const float* wr = &Wn[(size_t)(k0 + brow) * O_DIM + obase + bcol];
        w0 = *(const float4*)wr;
        w1 = *(const float4*)(wr + 32);
    };
    auto sts = [&](int buf, uint4 a0, uint4 a1, float4 w0, float4 w1) {
        *(uint4*)&As[buf][arow][acol]      = a0;
        *(uint4*)&As[buf][arow][acol + 64] = a1;
        *(uint2*)&Bs[buf][brow][bcol]      = make_uint2(pack2h(w0.x, w0.y), pack2h(w0.z, w0.w));
        *(uint2*)&Bs[buf][brow][bcol + 32] = make_uint2(pack2h(w1.x, w1.y), pack2h(w1.z, w1.w));
    };
    auto compute = [&](int buf) {
#pragma unroll
        for (int ksb = 0; ksb < 2; ksb++) {
            uint32_t af[4][4], bf[4];
#pragma unroll
            for (int mt = 0; mt < 4; mt++)
                ldsm4t(af[mt], sptr(&As[buf][ksb * 16 + a_krow][wm + mt * 16 + a_mcol]));
            ldsm4t(bf, sptr(&Bs[buf][ksb * 16 + b_krow][wn + b_ncol]));
#pragma unroll
            for (int mt = 0; mt < 4; mt++)
#pragma unroll
                for (int nt = 0; nt < 2; nt++)
                    mma16816h(acc[mt][nt], af[mt], &bf[nt * 2]);
        }
    };

    uint4 A00, A01, A10, A11;
    float4 W00, W01, W10, W11;
    ldg(0, A00, A01, W00, W01);
    sts(0, A00, A01, W00, W01);
    ldg(1, A00, A01, W00, W01);
    __syncthreads();

    const int NCHUNK = KSPL / 32;  // 32
    for (int ch = 0; ch < NCHUNK; ch += 2) {
        if (ch + 2 < NCHUNK) ldg(ch + 2, A10, A11, W10, W11);
        compute(0);
        sts(1, A00, A01, W00, W01);
        __syncthreads();
        if (ch + 3 < NCHUNK) ldg(ch + 3, A00, A01, W00, W01);
        compute(1);
        if (ch + 2 < NCHUNK) sts(0, A10, A11, W10, W11);
        __syncthreads();
    }

    // epilogue: Hp -> fp16, row-major [B][NO]; bias only in split 0
    const int r = lane >> 2, c = (lane & 3) * 2;
#pragma unroll
    for (int mt = 0; mt < 4; mt++)
#pragma unroll
        for (int nt = 0; nt < 2; nt++) {
            int ocol = obase + wn + nt * 8 + c;
            float bv0 = ks ? 0.0f : bias[n * O_DIM + ocol];
            float bv1 = ks ? 0.0f : bias[n * O_DIM + ocol + 1];
            int b0 = bbase + wm + mt * 16 + r;
#pragma unroll
            for (int q = 0; q < 2; q++) {
                size_t base = (size_t)(b0 + q*8) * NO_DIM + (size_t)n * O_DIM + ocol;
                *(uint32_t*)&Hdst[base] =
                    pack2h(acc[mt][nt][q*2] + bv0, acc[mt][nt][q*2+1] + bv1);
            }
        }
}

// ---------------------------------------------------------------- GEMM2 split-K (fp16, BK=16, prefetch-2, occ 2)
// A = H0 + H1 (combined at smem fill time)
__global__ __launch_bounds__(256, 2) void gemm2_kernel(const float* __restrict__ W3)
{
    __shared__ alignas(16) unsigned short As[2][128][24];   // 12 KB
    __shared__ alignas(16) unsigned short Bs[2][16][136];   // 8.5 KB

    const int s = blockIdx.z, bbase = blockIdx.x * 128, ebase = blockIdx.y * 128;
    const int tid = threadIdx.x, lane = tid & 31, warp = tid >> 5;
    const int wm = (warp & 1) * 64, wn = (warp >> 1) * 32;
    const int arow = tid >> 1, ahalf = (tid & 1) * 8;
    const int kkB = tid >> 5, colB = (tid & 31) * 4;
    const int g8 = lane >> 3, i8 = lane & 7;
    const int a_mrow = (g8 & 1) * 8 + i8, a_kcol = (g8 >> 1) * 8;
    const int b_krow = (g8 & 1) * 8 + i8, b_ncol = (g8 >> 1) * 8;

    float acc[4][4][4];
#pragma unroll
    for (int i = 0; i < 4; i++)
#pragma unroll
        for (int j = 0; j < 4; j++)
#pragma unroll
            for (int q = 0; q < 4; q++) acc[i][j][q] = 0.0f;

    const int kbeg = s * 256;

    auto ldg = [&](int ch, uint4& a0, uint4& a1, float4& p0, float4& p1) {
        int k0 = kbeg + ch * 16;
        size_t off = (size_t)(bbase + arow) * NO_DIM + k0 + ahalf;
        a0 = *(const uint4*)&g_H0[off];
        a1 = *(const uint4*)&g_H1[off];
        p0 = *(const float4*)&W3[(size_t)(k0 + kkB) * E_DIM + ebase + colB];
        p1 = *(const float4*)&W3[(size_t)(k0 + kkB + 8) * E_DIM + ebase + colB];
    };
    auto sts = [&](int buf, uint4 a0, uint4 a1, float4 p0, float4 p1) {
        uint4 c;
        c.x = h2add(a0.x, a1.x); c.y = h2add(a0.y, a1.y);
        c.z = h2add(a0.z, a1.z); c.w = h2add(a0.w, a1.w);
        *(uint4*)&As[buf][arow][ahalf] = c;
        *(uint2*)&Bs[buf][kkB][colB]     = make_uint2(pack2h(p0.x, p0.y), pack2h(p0.z, p0.w));
        *(uint2*)&Bs[buf][kkB + 8][colB] = make_uint2(pack2h(p1.x, p1.y), pack2h(p1.z, p1.w));
    };
    auto compute = [&](int buf) {
        uint32_t af[4][4], bfv[2][4];
#pragma unroll
        for (int mt = 0; mt < 4; mt++)
            ldsm4(af[mt], sptr(&As[buf][wm + mt * 16 + a_mrow][a_kcol]));
#pragma unroll
        for (int np = 0; np < 2; np++)
            ldsm4t(bfv[np], sptr(&Bs[buf][b_krow][wn + np * 16 + b_ncol]));
#pragma unroll
        for (int mt = 0; mt < 4; mt++)
#pragma unroll
            for (int nt = 0; nt < 4; nt++)
                mma16816h(acc[mt][nt], af[mt], &bfv[nt >> 1][(nt & 1) * 2]);
    };

    uint4 Ah0, Al0, Ah1, Al1;
    float4 B00, B01, B10, B11;
    ldg(0, Ah0, Al0, B00, B01);
    sts(0, Ah0, Al0, B00, B01);
    ldg(1, Ah0, Al0, B00, B01);
    __syncthreads();

    const int NCHUNK = 16;
    for (int ch = 0; ch < NCHUNK; ch += 2) {
        if (ch + 2 < NCHUNK) ldg(ch + 2, Ah1, Al1, B10, B11);
        compute(0);
        sts(1, Ah0, Al0, B00, B01);
        __syncthreads();
        if (ch + 3 < NCHUNK) ldg(ch + 3, Ah0, Al0, B00, B01);
        compute(1);
        if (ch + 2 < NCHUNK) sts(0, Ah1, Al1, B10, B11);
        __syncthreads();
    }

    float* Ps = g_P + (size_t)s * B_DIM * E_DIM;
    const int r = lane >> 2, c = (lane & 3) * 2;
#pragma unroll
    for (int mt = 0; mt < 4; mt++)
#pragma unroll
        for (int nt = 0; nt < 4; nt++) {
            int ecol = ebase + wn + nt * 8 + c;
            int b0 = bbase + wm + mt * 16 + r;
            *(float2*)&Ps[(size_t)b0 * E_DIM + ecol] = make_float2(acc[mt][nt][0], acc[mt][nt][1]);
            *(float2*)&Ps[(size_t)(b0 + 8) * E_DIM + ecol] = make_float2(acc[mt][nt][2], acc[mt][nt][3]);
        }
}

// ---------------------------------------------------------------- reduce (scalar, high-occupancy)
__global__ __launch_bounds__(256) void reduce_kernel(const float* __restrict__ b3, float* __restrict__ out) {
    int i = blockIdx.x * 256 + threadIdx.x;     // 0..131071
    int e = i & (E_DIM - 1);
    float sum = b3[e];
#pragma unroll
    for (int s = 0; s < N_DIM; s++)
        sum += g_P[(size_t)s * (B_DIM * E_DIM) + i];
    out[i] = (sum >= 0.f) ? sum : NEG_SLOPE * sum;
}

// ----------------------------------------------------------------
extern "C" void kernel_launch(void* const* d_in, const int* in_sizes, int n_in,
                              void* d_out, int out_size) {
    const float* x    = (const float*)d_in[0];
    const int*   gidx = (const int*)  d_in[1];
    const float* W    = (const float*)d_in[2];
    const float* bias = (const float*)d_in[3];
    const float* W3   = (const float*)d_in[4];
    const float* b3   = (const float*)d_in[5];
    float* out = (float*)d_out;

    {
        dim3 grid(D_DIM / 64, B_DIM / 64);
        transpose_kernel<<<grid, 256>>>(x);
    }
    {
        dim3 grid(B_DIM / 128, O_DIM / 64, N_DIM * 2);   // (2,4,82) = 656 CTAs
        gemm1_kernel<<<grid, 256>>>(gidx, W, bias);
    }
    {
        dim3 grid(B_DIM / 128, E_DIM / 128, N_DIM);      // (2,4,41) = 328 CTAs
        gemm2_kernel<<<grid, 256>>>(W3);
    }
    {
        reduce_kernel<<<(B_DIM * E_DIM) / 256, 256>>>(b3, out);   // 512 blocks
    }
}

// round 15
// speedup vs baseline: 1.5065x; 1.0925x over previous
#include <cuda_runtime.h>
#include <cuda_fp16.h>
#include <cstdint>

#define B_DIM 256
#define D_DIM 65536
#define N_DIM 41
#define G_DIM 2048
#define KSPL  1024        // gemm1 K per split
#define O_DIM 256
#define E_DIM 512
#define NO_DIM (N_DIM * O_DIM)
#define NSPL2 37          // gemm2 k-splits (296 CTAs = one perfect wave at occ 2)
#define NEG_SLOPE 0.2f

// statics ~62 MB
__device__ unsigned short g_xT[(size_t)D_DIM * B_DIM];     // 32 MB fp16 bits
__device__ unsigned short g_H0[(size_t)B_DIM * NO_DIM];    // 5.4 MB fp16 partial (k 0..1023)
__device__ unsigned short g_H1[(size_t)B_DIM * NO_DIM];    // 5.4 MB fp16 partial (k 1024..2047)
__device__ float g_P[(size_t)NSPL2 * B_DIM * E_DIM];       // 19.4 MB

// ---------------------------------------------------------------- helpers
__device__ __forceinline__ uint32_t sptr(const void* p) {
    return (uint32_t)__cvta_generic_to_shared(p);
}
__device__ __forceinline__ void ldsm4t(uint32_t* r, uint32_t a) {
    asm volatile("ldmatrix.sync.aligned.m8n8.x4.trans.shared.b16 {%0,%1,%2,%3},[%4];"
                 : "=r"(r[0]), "=r"(r[1]), "=r"(r[2]), "=r"(r[3]) : "r"(a));
}
__device__ __forceinline__ void ldsm4(uint32_t* r, uint32_t a) {
    asm volatile("ldmatrix.sync.aligned.m8n8.x4.shared.b16 {%0,%1,%2,%3},[%4];"
                 : "=r"(r[0]), "=r"(r[1]), "=r"(r[2]), "=r"(r[3]) : "r"(a));
}
__device__ __forceinline__ void mma16816h(float* c, const uint32_t* a, const uint32_t* b) {
    asm volatile("mma.sync.aligned.m16n8k16.row.col.f32.f16.f16.f32 "
                 "{%0,%1,%2,%3},{%4,%5,%6,%7},{%8,%9},{%0,%1,%2,%3};"
                 : "+f"(c[0]), "+f"(c[1]), "+f"(c[2]), "+f"(c[3])
                 : "r"(a[0]), "r"(a[1]), "r"(a[2]), "r"(a[3]), "r"(b[0]), "r"(b[1]));
}
__device__ __forceinline__ uint32_t pack2h(float a, float b) {
    return (uint32_t)__half_as_ushort(__float2half_rn(a)) |
           ((uint32_t)__half_as_ushort(__float2half_rn(b)) << 16);
}
__device__ __forceinline__ uint32_t h2add(uint32_t a, uint32_t b) {
    __half2 r = __hadd2(*(__half2*)&a, *(__half2*)&b);
    return *(uint32_t*)&r;
}

// ---------------------------------------------------------------- transpose x -> fp16 xT [D][B]
__global__ __launch_bounds__(256) void transpose_kernel(const float* __restrict__ x) {
    __shared__ float tile[64][65];
    int d0 = blockIdx.x * 64, b0 = blockIdx.y * 64;
    int t = threadIdx.x;
    int br = t / 16, dc = (t % 16) * 4;
#pragma unroll
    for (int p = 0; p < 4; p++) {
        int b = br + p * 16;
        float4 v = *(const float4*)&x[(size_t)(b0 + b) * D_DIM + d0 + dc];
        tile[b][dc] = v.x; tile[b][dc+1] = v.y; tile[b][dc+2] = v.z; tile[b][dc+3] = v.w;
    }
    __syncthreads();
    int dr = t / 16, bc = (t % 16) * 4;
#pragma unroll
    for (int p = 0; p < 4; p++) {
        int d = dr + p * 16;
        size_t off = (size_t)(d0 + d) * B_DIM + b0 + bc;
        *(uint2*)&g_xT[off] = make_uint2(pack2h(tile[bc][d],   tile[bc+1][d]),
                                         pack2h(tile[bc+2][d], tile[bc+3][d]));
    }
}

// ---------------------------------------------------------------- GEMM1 (fp16, tile 128x64, BK=32, prefetch-2, occ 2, K-split 2)
__global__ __launch_bounds__(256, 2) void gemm1_kernel(
    const int* __restrict__ gidx, const float* __restrict__ W, const float* __restrict__ bias)
{
    __shared__ unsigned short sIdx[KSPL];                       // 2 KB
    __shared__ alignas(16) unsigned short As[2][32][136];       // 17.4 KB
    __shared__ alignas(16) unsigned short Bs[2][32][72];        // 9.2 KB

    const int zz    = blockIdx.z;
    const int n     = zz >> 1;
    const int ks    = zz & 1;
    const int kbeg  = ks * KSPL;
    const int bbase = blockIdx.x * 128;
    const int obase = blockIdx.y * 64;
    const int tid = threadIdx.x, lane = tid & 31, warp = tid >> 5;
    const int wm = (warp & 1) * 64, wn = (warp >> 1) * 16;
    const int arow = tid >> 3, acol = (tid & 7) * 8;
    const int brow = tid >> 3, bcol = (tid & 7) * 4;

    for (int i = tid; i < KSPL; i += 256)
        sIdx[i] = (unsigned short)gidx[(size_t)n * G_DIM + kbeg + i];
    __syncthreads();

    const float* Wn = W + (size_t)n * G_DIM * O_DIM + (size_t)kbeg * O_DIM;
    unsigned short* Hdst = ks ? g_H1 : g_H0;
    const int g8 = lane >> 3, i8 = lane & 7;
    const int a_krow = (g8 >> 1) * 8 + i8, a_mcol = (g8 & 1) * 8;
    const int b_krow = (g8 & 1) * 8 + i8, b_ncol = (g8 >> 1) * 8;

    float acc[4][2][4];
#pragma unroll
    for (int i = 0; i < 4; i++)
#pragma unroll
        for (int j = 0; j < 2; j++)
#pragma unroll
            for (int q = 0; q < 4; q++) acc[i][j][q] = 0.0f;

    auto ldg = [&](int ch, uint4& a0, uint4& a1, float4& w0, float4& w1) {
        int k0 = ch * 32;
        int gi = sIdx[k0 + arow];
        const unsigned short* xr = &g_xT[(size_t)gi * B_DIM + bbase + acol];
        a0 = *(const uint4*)xr;
        a1 = *(const uint4*)(xr + 64);
        const float* wr = &Wn[(size_t)(k0 + brow) * O_DIM + obase + bcol];
        w0 = *(const float4*)wr;
        w1 = *(const float4*)(wr + 32);
    };
    auto sts = [&](int buf, uint4 a0, uint4 a1, float4 w0, float4 w1) {
        *(uint4*)&As[buf][arow][acol]      = a0;
        *(uint4*)&As[buf][arow][acol + 64] = a1;
        *(uint2*)&Bs[buf][brow][bcol]      = make_uint2(pack2h(w0.x, w0.y), pack2h(w0.z, w0.w));
        *(uint2*)&Bs[buf][brow][bcol + 32] = make_uint2(pack2h(w1.x, w1.y), pack2h(w1.z, w1.w));
    };
    auto compute = [&](int buf) {
#pragma unroll
        for (int ksb = 0; ksb < 2; ksb++) {
            uint32_t af[4][4], bf[4];
#pragma unroll
            for (int mt = 0; mt < 4; mt++)
                ldsm4t(af[mt], sptr(&As[buf][ksb * 16 + a_krow][wm + mt * 16 + a_mcol]));
            ldsm4t(bf, sptr(&Bs[buf][ksb * 16 + b_krow][wn + b_ncol]));
#pragma unroll
            for (int mt = 0; mt < 4; mt++)
#pragma unroll
                for (int nt = 0; nt < 2; nt++)
                    mma16816h(acc[mt][nt], af[mt], &bf[nt * 2]);
        }
    };

    uint4 A00, A01, A10, A11;
    float4 W00, W01, W10, W11;
    ldg(0, A00, A01, W00, W01);
    sts(0, A00, A01, W00, W01);
    ldg(1, A00, A01, W00, W01);
    __syncthreads();

    const int NCHUNK = KSPL / 32;  // 32
    for (int ch = 0; ch < NCHUNK; ch += 2) {
        if (ch + 2 < NCHUNK) ldg(ch + 2, A10, A11, W10, W11);
        compute(0);
        sts(1, A00, A01, W00, W01);
        __syncthreads();
        if (ch + 3 < NCHUNK) ldg(ch + 3, A00, A01, W00, W01);
        compute(1);
        if (ch + 2 < NCHUNK) sts(0, A10, A11, W10, W11);
        __syncthreads();
    }

    // epilogue: Hp -> fp16, row-major [B][NO]; bias only in split 0
    const int r = lane >> 2, c = (lane & 3) * 2;
#pragma unroll
    for (int mt = 0; mt < 4; mt++)
#pragma unroll
        for (int nt = 0; nt < 2; nt++) {
            int ocol = obase + wn + nt * 8 + c;
            float bv0 = ks ? 0.0f : bias[n * O_DIM + ocol];
            float bv1 = ks ? 0.0f : bias[n * O_DIM + ocol + 1];
            int b0 = bbase + wm + mt * 16 + r;
#pragma unroll
            for (int q = 0; q < 2; q++) {
                size_t base = (size_t)(b0 + q*8) * NO_DIM + (size_t)n * O_DIM + ocol;
                *(uint32_t*)&Hdst[base] =
                    pack2h(acc[mt][nt][q*2] + bv0, acc[mt][nt][q*2+1] + bv1);
            }
        }
}

// ---------------------------------------------------------------- GEMM2 (fp16, BK=16, prefetch-2, occ 2, 37 balanced K-splits)
// split s covers chunk-pairs [9s, 9s+9) for s<32, [8s+32, 8s+40) for s>=32
__global__ __launch_bounds__(256, 2) void gemm2_kernel(const float* __restrict__ W3)
{
    __shared__ alignas(16) unsigned short As[2][128][24];   // 12 KB
    __shared__ alignas(16) unsigned short Bs[2][16][136];   // 8.5 KB

    const int s = blockIdx.z, bbase = blockIdx.x * 128, ebase = blockIdx.y * 128;
    const int pair0  = (s < 32) ? 9 * s : 8 * s + 32;
    const int npairs = (s < 32) ? 9 : 8;
    const int kbeg   = pair0 * 32;
    const int NCHUNK = npairs * 2;            // 18 or 16 (even)

    const int tid = threadIdx.x, lane = tid & 31, warp = tid >> 5;
    const int wm = (warp & 1) * 64, wn = (warp >> 1) * 32;
    const int arow = tid >> 1, ahalf = (tid & 1) * 8;
    const int kkB = tid >> 5, colB = (tid & 31) * 4;
    const int g8 = lane >> 3, i8 = lane & 7;
    const int a_mrow = (g8 & 1) * 8 + i8, a_kcol = (g8 >> 1) * 8;
    const int b_krow = (g8 & 1) * 8 + i8, b_ncol = (g8 >> 1) * 8;

    float acc[4][4][4];
#pragma unroll
    for (int i = 0; i < 4; i++)
#pragma unroll
        for (int j = 0; j < 4; j++)
#pragma unroll
            for (int q = 0; q < 4; q++) acc[i][j][q] = 0.0f;

    auto ldg = [&](int ch, uint4& a0, uint4& a1, float4& p0, float4& p1) {
        int k0 = kbeg + ch * 16;
        size_t off = (size_t)(bbase + arow) * NO_DIM + k0 + ahalf;
        a0 = *(const uint4*)&g_H0[off];
        a1 = *(const uint4*)&g_H1[off];
        p0 = *(const float4*)&W3[(size_t)(k0 + kkB) * E_DIM + ebase + colB];
        p1 = *(const float4*)&W3[(size_t)(k0 + kkB + 8) * E_DIM + ebase + colB];
    };
    auto sts = [&](int buf, uint4 a0, uint4 a1, float4 p0, float4 p1) {
        uint4 c;
        c.x = h2add(a0.x, a1.x); c.y = h2add(a0.y, a1.y);
        c.z = h2add(a0.z, a1.z); c.w = h2add(a0.w, a1.w);
        *(uint4*)&As[buf][arow][ahalf] = c;
        *(uint2*)&Bs[buf][kkB][colB]     = make_uint2(pack2h(p0.x, p0.y), pack2h(p0.z, p0.w));
        *(uint2*)&Bs[buf][kkB + 8][colB] = make_uint2(pack2h(p1.x, p1.y), pack2h(p1.z, p1.w));
    };
    auto compute = [&](int buf) {
        uint32_t af[4][4], bfv[2][4];
#pragma unroll
        for (int mt = 0; mt < 4; mt++)
            ldsm4(af[mt], sptr(&As[buf][wm + mt * 16 + a_mrow][a_kcol]));
#pragma unroll
        for (int np = 0; np < 2; np++)
            ldsm4t(bfv[np], sptr(&Bs[buf][b_krow][wn + np * 16 + b_ncol]));
#pragma unroll
        for (int mt = 0; mt < 4; mt++)
#pragma unroll
            for (int nt = 0; nt < 4; nt++)
                mma16816h(acc[mt][nt], af[mt], &bfv[nt >> 1][(nt & 1) * 2]);
    };

    uint4 Ah0, Al0, Ah1, Al1;
    float4 B00, B01, B10, B11;
    ldg(0, Ah0, Al0, B00, B01);
    sts(0, Ah0, Al0, B00, B01);
    ldg(1, Ah0, Al0, B00, B01);
    __syncthreads();

    for (int ch = 0; ch < NCHUNK; ch += 2) {
        if (ch + 2 < NCHUNK) ldg(ch + 2, Ah1, Al1, B10, B11);
        compute(0);
        sts(1, Ah0, Al0, B00, B01);
        __syncthreads();
        if (ch + 3 < NCHUNK) ldg(ch + 3, Ah0, Al0, B00, B01);
        compute(1);
        if (ch + 2 < NCHUNK) sts(0, Ah1, Al1, B10, B11);
        __syncthreads();
    }

    float* Ps = g_P + (size_t)s * B_DIM * E_DIM;
    const int r = lane >> 2, c = (lane & 3) * 2;
#pragma unroll
    for (int mt = 0; mt < 4; mt++)
#pragma unroll
        for (int nt = 0; nt < 4; nt++) {
            int ecol = ebase + wn + nt * 8 + c;
            int b0 = bbase + wm + mt * 16 + r;
            *(float2*)&Ps[(size_t)b0 * E_DIM + ecol] = make_float2(acc[mt][nt][0], acc[mt][nt][1]);
            *(float2*)&Ps[(size_t)(b0 + 8) * E_DIM + ecol] = make_float2(acc[mt][nt][2], acc[mt][nt][3]);
        }
}

// ---------------------------------------------------------------- reduce (scalar, high-occupancy)
__global__ __launch_bounds__(256) void reduce_kernel(const float* __restrict__ b3, float* __restrict__ out) {
    int i = blockIdx.x * 256 + threadIdx.x;     // 0..131071
    int e = i & (E_DIM - 1);
    float sum = b3[e];
#pragma unroll
    for (int s = 0; s < NSPL2; s++)
        sum += g_P[(size_t)s * (B_DIM * E_DIM) + i];
    out[i] = (sum >= 0.f) ? sum : NEG_SLOPE * sum;
}

// ----------------------------------------------------------------
extern "C" void kernel_launch(void* const* d_in, const int* in_sizes, int n_in,
                              void* d_out, int out_size) {
    const float* x    = (const float*)d_in[0];
    const int*   gidx = (const int*)  d_in[1];
    const float* W    = (const float*)d_in[2];
    const float* bias = (const float*)d_in[3];
    const float* W3   = (const float*)d_in[4];
    const float* b3   = (const float*)d_in[5];
    float* out = (float*)d_out;

    {
        dim3 grid(D_DIM / 64, B_DIM / 64);
        transpose_kernel<<<grid, 256>>>(x);
    }
    {
        dim3 grid(B_DIM / 128, O_DIM / 64, N_DIM * 2);   // (2,4,82) = 656 CTAs
        gemm1_kernel<<<grid, 256>>>(gidx, W, bias);
    }
    {
        dim3 grid(B_DIM / 128, E_DIM / 128, NSPL2);      // (2,4,37) = 296 CTAs = 1 wave
        gemm2_kernel<<<grid, 256>>>(W3);
    }
    {
        reduce_kernel<<<(B_DIM * E_DIM) / 256, 256>>>(b3, out);   // 512 blocks
    }
}